// round 14
// baseline (speedup 1.0000x reference)
#include <cuda_runtime.h>
#include <cuda_fp16.h>
#include <cstdint>

// ---------------- constants ----------------
#define NVAR   64
#define HID1   256
#define HID2   128
#define BATCH  16384
#define BT     64
#define NCTA   (BATCH / BT)        // 256 CTAs -> 2 per SM, all 148 SMs used
#define KTMAX  4
#define HSH    264                 // sH row stride (halfs)
#define YCS    72                  // Yc column stride (halfs); 144B, 16B-aligned

// SMEM byte offsets (all 16B aligned)
#define OFF_YC   0                         // 67 cols x 72 halfs = 9648 (pad 9728)
#define OFF_H    9728                      // 64 x 264 halfs     = 33792
#define OFF_W1   43520                     // 32768 (ktc<=4)
#define OFF_W2   76288                     // 32768 (one K-half slot)
#define OFF_COLS 109056                    // 2 x 80 ints (pad 768)
#define OFF_B1   109824                    // 2 x 256 f = 2048
#define OFF_B2   111872                    // 2 x 128 f = 1024
#define OFF_W3   112896                    // 2 x 128 f = 1024
#define OFF_B3   113920                    // 2 f (+pad 16)
#define OFF_SP   113936                    // 4 x 64 f = 1024
#define SMEM_TOTAL 114960                  // x2 CTAs = 229920 <= 228KB SM budget

// ---------------- device scratch ----------------
__device__ __half g_W1h[NVAR * 16384];     // packed compact-K frag-major (4096*ktc halfs/var)
__device__ __half g_W2h[NVAR * 32768];     // per-var W2: h0 = halfs [0,16384), h1 = [16384,32768)
__device__ __half g_Uth[NVAR * BATCH];
__device__ int    g_plist[NVAR * NVAR];
__device__ int    g_pcnt[NVAR];
__device__ int    g_KT[NVAR];
__device__ int    g_off1[NVAR];
__device__ int    g_cols[NVAR * 80];       // per-var Yc column index per compact-k

// ---------------- helpers ----------------
static __device__ __forceinline__ void mma16(float* c, const unsigned* a,
                                             unsigned b0, unsigned b1) {
    asm volatile(
        "mma.sync.aligned.m16n8k16.row.col.f32.f16.f16.f32 "
        "{%0,%1,%2,%3},{%4,%5,%6,%7},{%8,%9},{%0,%1,%2,%3};\n"
        : "+f"(c[0]), "+f"(c[1]), "+f"(c[2]), "+f"(c[3])
        : "r"(a[0]), "r"(a[1]), "r"(a[2]), "r"(a[3]), "r"(b0), "r"(b1));
}

static __device__ __forceinline__ void ldmA(unsigned* a, uint32_t saddr) {
    asm volatile("ldmatrix.sync.aligned.m8n8.x4.shared.b16 {%0,%1,%2,%3}, [%4];"
        : "=r"(a[0]), "=r"(a[1]), "=r"(a[2]), "=r"(a[3]) : "r"(saddr));
}
static __device__ __forceinline__ void ldmT(unsigned* a, uint32_t saddr) {
    asm volatile("ldmatrix.sync.aligned.m8n8.x4.trans.shared.b16 {%0,%1,%2,%3}, [%4];"
        : "=r"(a[0]), "=r"(a[1]), "=r"(a[2]), "=r"(a[3]) : "r"(saddr));
}

static __device__ __forceinline__ void cp16(void* sdst, const void* gsrc) {
    unsigned sa = (unsigned)__cvta_generic_to_shared(sdst);
    asm volatile("cp.async.cg.shared.global [%0], [%1], 16;\n" :: "r"(sa), "l"(gsrc));
}

#define CP_COMMIT() asm volatile("cp.async.commit_group;\n" ::: "memory")
#define CP_WAIT0()  asm volatile("cp.async.wait_group 0;\n" ::: "memory")
#define BAR_SYNC(id, n) asm volatile("bar.sync %0, %1;" :: "r"(id), "r"(n) : "memory")

// ---------------- prep kernels (layouts identical to R12) ----------------
__global__ void sen_prep_meta(const int* __restrict__ G) {
    int i = threadIdx.x;
    int np = 0;
    for (int j = 0; j < i; ++j)
        if (G[j * NVAR + i] > 0) g_plist[i * NVAR + np++] = j;
    g_pcnt[i] = np;
    g_KT[i] = (np + 16) / 16;          // ceil((np+1)/16) <= 4
    for (int k = 0; k < 80; ++k) {
        int c;
        if (k < np)       c = g_plist[i * NVAR + k];
        else if (k == np) c = 64 + (i & 1);   // u column (parity)
        else              c = 66;             // zero column
        g_cols[i * 80 + k] = c;
    }
    __syncthreads();
    if (i == 0) {
        int off = 0;
        for (int v = 0; v < NVAR; ++v) { g_off1[v] = off; off += 4096 * g_KT[v]; }
    }
}

// W1 packed compact-K frag-major: chunk(i) = [hf=2][n4g=8][kt=ktc][lane=32][8 halfs]
__global__ void sen_prep_w1h(const float* __restrict__ W1) {
    int idx = blockIdx.x * blockDim.x + threadIdx.x;
    if (idx >= NVAR * 16384) return;
    int i    = idx / 16384;
    int rem  = idx % 16384;
    int hf   = rem / 8192;
    int rem2 = rem % 8192;
    int n4g  = rem2 / 1024;
    int rem3 = rem2 % 1024;
    int kt   = rem3 / 256;
    int f    = rem3 % 256;
    int lane = f >> 3, h = f & 7;
    int ktc = g_KT[i];
    if (kt >= ktc) return;
    int n8l = h >> 2, p = (h >> 1) & 1, e = h & 1;
    int k = kt * 16 + (lane & 3) * 2 + 8 * p + e;
    int n = hf * 128 + n4g * 16 + n8l * 8 + (lane >> 2);
    int np = g_pcnt[i];
    float val = 0.f;
    if (k < np)       val = W1[(i * (NVAR + 1) + g_plist[i * NVAR + k]) * HID1 + n];
    else if (k == np) val = W1[(i * (NVAR + 1) + NVAR) * HID1 + n];
    int dst = g_off1[i] + ((hf * 8 + n4g) * ktc + kt) * 256 + lane * 8 + h;
    g_W1h[dst] = __float2half_rn(val);
}

// W2 frag-major per var: [hf=2][n4g=8][kt=8][lane=32][8 halfs]
__global__ void sen_prep_w2h(const float* __restrict__ W2) {
    int idx = blockIdx.x * blockDim.x + threadIdx.x;
    if (idx >= NVAR * 32768) return;
    int i    = idx / 32768;
    int rem  = idx % 32768;
    int hf   = rem / 16384;
    int rem2 = rem % 16384;
    int n4g  = rem2 / 2048;
    int rem3 = rem2 % 2048;
    int kt   = rem3 / 256;
    int f    = rem3 % 256;
    int lane = f >> 3, h = f & 7;
    int n8l = h >> 2, p = (h >> 1) & 1, e = h & 1;
    int k = hf * 128 + kt * 16 + (lane & 3) * 2 + 8 * p + e;
    int n = n4g * 16 + n8l * 8 + (lane >> 2);
    g_W2h[idx] = __float2half_rn(W2[(i * HID1 + k) * HID2 + n]);
}

__global__ void sen_prep_ut(const float* __restrict__ U) {
    int idx = blockIdx.x * blockDim.x + threadIdx.x;
    if (idx >= NVAR * BATCH) return;
    int v = idx / BATCH;
    int b = idx - v * BATCH;
    g_Uth[idx] = __float2half_rn(U[b * NVAR + v]);
}

// ---------------- main kernel: 256 threads, BT=64, 2 CTAs/SM ----------------
__global__ void __launch_bounds__(256, 2) sen_main(
    const float* __restrict__ X,
    const float* __restrict__ b1g,
    const float* __restrict__ b2g,
    const float* __restrict__ W3g,
    const float* __restrict__ b3g,
    float* __restrict__ out)
{
    extern __shared__ char smem[];
    __half* Yc   = (__half*)(smem + OFF_YC);
    __half* sH   = (__half*)(smem + OFF_H);
    int*   sCols = (int*)  (smem + OFF_COLS);
    float*  sB1  = (float*)(smem + OFF_B1);
    float*  sB2  = (float*)(smem + OFF_B2);
    float*  sW3  = (float*)(smem + OFF_W3);
    float*  sB3  = (float*)(smem + OFF_B3);
    float*  sP   = (float*)(smem + OFF_SP);
    const uint32_t smb = (uint32_t)__cvta_generic_to_shared(smem);
    const uint32_t ycb = smb + OFF_YC;

    const int tid  = threadIdx.x;
    const int lane = tid & 31;
    const int w    = tid >> 5;
    const int wm   = w >> 2;                // M group 0..1 (rows 32*wm..+32)
    const int wn   = w & 3;                 // N group 0..3
    const int b0   = blockIdx.x * BT;
    const int r0   = 32 * wm + (lane >> 2);
    const int ccol = (lane & 3) * 2;
    // indexed-ldmatrix lane params (same derivation as R12)
    const int laneoff = ((lane >> 4) << 3) + (lane & 7);
    const uint32_t rowb2 = (uint32_t)(32 * wm + ((lane >> 3) & 1) * 8) * 2;

    const uint32_t aHb = smb + OFF_H +
        ((((32 * wm + (lane & 15)) * HSH) + (lane >> 4) * 8) << 1);

    // init Yc cols 0..63 from X (column-major)
    for (int idx = tid; idx < NVAR * BT; idx += 256) {
        int v = idx >> 6, r = idx & 63;
        Yc[v * YCS + r] = __float2half_rn(X[(size_t)(b0 + r) * NVAR + v]);
    }
    // zero cols 64..66
    for (int idx = tid; idx < 3 * YCS; idx += 256) {
        int c = 64 + idx / YCS, p = idx % YCS;
        Yc[c * YCS + p] = __half(0.f);
    }
    __syncthreads();
    if (tid < 8) {    // u_0 into col 64 (parity 0): 64 halfs = 8 uint4
        uint4 v = *(const uint4*)(g_Uth + b0 + tid * 8);
        *(uint4*)(Yc + 64 * YCS + tid * 8) = v;
    }
    if (tid < 80) sCols[tid] = __ldg(g_cols + tid);
    sB1[tid] = __ldg(b1g + tid);
    if (tid < 128) { sB2[tid] = __ldg(b2g + tid); sW3[tid] = __ldg(W3g + tid); }
    if (tid == 0) sB3[0] = __ldg(b3g);
    // issue W1(0)
    {
        const int kt0 = __ldg(g_KT);
        const char* s1 = (const char*)g_W1h;
        for (int idx = tid; idx < kt0 * 512; idx += 256)
            cp16(smem + OFF_W1 + idx * 16, s1 + idx * 16);
        CP_COMMIT();
    }

    float acc2[2][4][4];
    #pragma unroll
    for (int m = 0; m < 2; ++m)
        #pragma unroll
        for (int n = 0; n < 4; ++n)
            #pragma unroll
            for (int e = 0; e < 4; ++e) acc2[m][n][e] = 0.f;

// L1 one N-half (128 cols): warp covers cols HF*128 + wn*32..+32
#define L1H(KTC, HF)                                                         \
    _Pragma("unroll")                                                        \
    for (int m = 0; m < 2; ++m)                                              \
        _Pragma("unroll")                                                    \
        for (int n = 0; n < 4; ++n)                                          \
            _Pragma("unroll")                                                \
            for (int e = 0; e < 4; ++e) c1[m][n][e] = 0.f;                   \
    _Pragma("unroll")                                                        \
    for (int kt = 0; kt < (KTC); ++kt) {                                     \
        unsigned a0[4], a1[4];                                               \
        const int sc = scp[kt * 16 + laneoff];                               \
        const uint32_t aA = ycb + (uint32_t)sc * (YCS * 2) + rowb2;          \
        ldmT(a0, aA);          /* rows 32wm..+15   */                        \
        ldmT(a1, aA + 32);     /* rows 32wm+16..+31 */                       \
        _Pragma("unroll")                                                    \
        for (int n4 = 0; n4 < 2; ++n4) {                                     \
            uint4 bb = *(const uint4*)(smem + OFF_W1 +                       \
                ((((((HF) * 8 + wn * 2 + n4) * (KTC)) + kt) * 32 + lane) << 4)); \
            mma16(c1[0][n4 * 2],     a0, bb.x, bb.y);                        \
            mma16(c1[0][n4 * 2 + 1], a0, bb.z, bb.w);                        \
            mma16(c1[1][n4 * 2],     a1, bb.x, bb.y);                        \
            mma16(c1[1][n4 * 2 + 1], a1, bb.z, bb.w);                        \
        }                                                                    \
    }

#define EPI(HF) {                                                            \
    const float* B1 = sB1 + pb * 256;                                        \
    _Pragma("unroll")                                                        \
    for (int Mt = 0; Mt < 2; ++Mt) {                                         \
        const int rA = r0 + 16 * Mt;                                         \
        _Pragma("unroll")                                                    \
        for (int n = 0; n < 4; ++n) {                                        \
            const int c = (HF) * 128 + wn * 32 + n * 8 + ccol;               \
            const float bi0 = B1[c], bi1 = B1[c + 1];                        \
            __half2 hA = __floats2half2_rn(fmaxf(c1[Mt][n][0] + bi0, 0.f),   \
                                           fmaxf(c1[Mt][n][1] + bi1, 0.f));  \
            __half2 hB = __floats2half2_rn(fmaxf(c1[Mt][n][2] + bi0, 0.f),   \
                                           fmaxf(c1[Mt][n][3] + bi1, 0.f));  \
            *(__half2*)(sH + rA * HSH + c)       = hA;                       \
            *(__half2*)(sH + (rA + 8) * HSH + c) = hB;                       \
        } } }

// L2 one K-half from the single W2 slot (slot holds K-cols HF*128..+128)
#define L2H(HF)                                                              \
    _Pragma("unroll")                                                        \
    for (int kt = 0; kt < 8; ++kt) {                                         \
        unsigned a0[4], a1[4];                                               \
        const uint32_t aH = aHb + ((HF) * 8 + kt) * 32;                      \
        ldmA(a0, aH);                                                        \
        ldmA(a1, aH + 16 * HSH * 2);                                         \
        _Pragma("unroll")                                                    \
        for (int n4 = 0; n4 < 2; ++n4) {                                     \
            uint4 bb = *(const uint4*)(smem + OFF_W2 +                       \
                ((((wn * 2 + n4) * 8 + kt) * 32 + lane) << 4));              \
            mma16(acc2[0][n4 * 2],     a0, bb.x, bb.y);                      \
            mma16(acc2[0][n4 * 2 + 1], a0, bb.z, bb.w);                      \
            mma16(acc2[1][n4 * 2],     a1, bb.x, bb.y);                      \
            mma16(acc2[1][n4 * 2 + 1], a1, bb.z, bb.w);                      \
        }                                                                    \
    }

    #pragma unroll 1
    for (int i = 0; i < NVAR; ++i) {
        const int pb  = i & 1;
        const int ktc = __ldg(g_KT + i);

        // S1: W1(i)+misc landed; Yc col i-1, u_i, sCols(i), biases(i) visible
        CP_WAIT0();
        __syncthreads();

        // ---- phase A: issue W2 h0(i) into slot; L1 + epilogue -> sH ----
        {
            const char* s2 = (const char*)(g_W2h + (size_t)i * 32768);
            for (int idx = tid; idx < 2048; idx += 256)
                cp16(smem + OFF_W2 + idx * 16, s2 + idx * 16);
            CP_COMMIT();
        }
        {
            const int* scp = sCols + pb * 80;
            float c1[2][4][4];
            switch (ktc) {
                case 1: L1H(1, 0) EPI(0) L1H(1, 1) EPI(1) break;
                case 2: L1H(2, 0) EPI(0) L1H(2, 1) EPI(1) break;
                case 3: L1H(3, 0) EPI(0) L1H(3, 1) EPI(1) break;
                default: L1H(4, 0) EPI(0) L1H(4, 1) EPI(1) break;
            }
        }

        // S2: sH complete + W2 h0 landed
        CP_WAIT0();
        __syncthreads();

        L2H(0)

        // S3: all warps done reading slot -> refill with h1; wait; publish
        __syncthreads();
        {
            const char* s2 = (const char*)(g_W2h + (size_t)i * 32768 + 16384);
            for (int idx = tid; idx < 2048; idx += 256)
                cp16(smem + OFF_W2 + idx * 16, s2 + idx * 16);
            CP_COMMIT();
        }
        CP_WAIT0();
        __syncthreads();

        // ---- phase B2: issue next-var W1/cols/biases/u; L2 K-half 1; L3 ----
        if (i + 1 < NVAR) {
            const int ktn = __ldg(g_KT + i + 1);
            const char* s1 = (const char*)(g_W1h + __ldg(g_off1 + i + 1));
            for (int idx = tid; idx < ktn * 512; idx += 256)
                cp16(smem + OFF_W1 + idx * 16, s1 + idx * 16);
            const int nb = (i + 1) & 1;
            sB1[nb * 256 + tid] = __ldg(b1g + (i + 1) * HID1 + tid);
            if (tid < 128) {
                sB2[nb * 128 + tid] = __ldg(b2g + (i + 1) * HID2 + tid);
                sW3[nb * 128 + tid] = __ldg(W3g + (i + 1) * HID2 + tid);
            }
            if (tid == 0) sB3[nb] = __ldg(b3g + i + 1);
            if (tid < 80) sCols[nb * 80 + tid] = __ldg(g_cols + (i + 1) * 80 + tid);
            if (tid < 8) {
                uint4 v = *(const uint4*)(g_Uth + (size_t)(i + 1) * BATCH + b0 + tid * 8);
                *(uint4*)(Yc + (64 + nb) * YCS + tid * 8) = v;
            }
        }
        CP_COMMIT();

        L2H(1)

        // ---- L3: y = relu(acc2 + b2) . w3 + b3 ----
        {
            const float* B2  = sB2 + pb * 128;
            const float* W3s = sW3 + pb * 128;
            float yv[2][2];
            #pragma unroll
            for (int Mt = 0; Mt < 2; ++Mt) {
                float pA = 0.f, pB = 0.f;
                #pragma unroll
                for (int n = 0; n < 4; ++n) {
                    const int c = wn * 32 + n * 8 + ccol;
                    const float w30 = W3s[c], w31 = W3s[c + 1];
                    const float d0 = B2[c], d1 = B2[c + 1];
                    pA = fmaf(fmaxf(acc2[Mt][n][0] + d0, 0.f), w30, pA);
                    pA = fmaf(fmaxf(acc2[Mt][n][1] + d1, 0.f), w31, pA);
                    pB = fmaf(fmaxf(acc2[Mt][n][2] + d0, 0.f), w30, pB);
                    pB = fmaf(fmaxf(acc2[Mt][n][3] + d1, 0.f), w31, pB);
                    acc2[Mt][n][0] = 0.f; acc2[Mt][n][1] = 0.f;
                    acc2[Mt][n][2] = 0.f; acc2[Mt][n][3] = 0.f;
                }
                pA += __shfl_xor_sync(0xffffffffu, pA, 1);
                pA += __shfl_xor_sync(0xffffffffu, pA, 2);
                pB += __shfl_xor_sync(0xffffffffu, pB, 1);
                pB += __shfl_xor_sync(0xffffffffu, pB, 2);
                yv[Mt][0] = pA; yv[Mt][1] = pB;
            }
            if ((lane & 3) == 0) {
                sP[wn * 64 + r0]      = yv[0][0];
                sP[wn * 64 + r0 + 8]  = yv[0][1];
                sP[wn * 64 + r0 + 16] = yv[1][0];
                sP[wn * 64 + r0 + 24] = yv[1][1];
            }
            BAR_SYNC(1 + wm, 128);   // wm-group local: 4 wn warps exchange partials
            if (wn == 0 && (lane & 3) == 0) {
                const float b3v = sB3[pb];
                #pragma unroll
                for (int s = 0; s < 4; ++s) {
                    const int r = r0 + 8 * s;
                    const float y = sP[r] + sP[64 + r] + sP[128 + r] + sP[192 + r] + b3v;
                    out[(size_t)(b0 + r) * NVAR + i] = y;
                    Yc[i * YCS + r] = __float2half_rn(y);
                }
            }
        }
        // next S1 (CTA-wide) publishes Yc col i / u / cols / biases before A(i+1)
    } // i
}

#undef L1H
#undef EPI
#undef L2H

// ---------------- launch ----------------
extern "C" void kernel_launch(void* const* d_in, const int* in_sizes, int n_in,
                              void* d_out, int out_size) {
    (void)in_sizes; (void)n_in; (void)out_size;
    const float* X  = (const float*)d_in[0];
    const float* U  = (const float*)d_in[1];
    const int*   G  = (const int*)  d_in[2];
    const float* W1 = (const float*)d_in[3];
    const float* b1 = (const float*)d_in[4];
    const float* W2 = (const float*)d_in[5];
    const float* b2 = (const float*)d_in[6];
    const float* W3 = (const float*)d_in[7];
    const float* b3 = (const float*)d_in[8];
    float* out = (float*)d_out;

    sen_prep_meta<<<1, NVAR>>>(G);
    sen_prep_w1h<<<(NVAR * 16384 + 255) / 256, 256>>>(W1);
    sen_prep_w2h<<<(NVAR * 32768 + 255) / 256, 256>>>(W2);
    sen_prep_ut<<<(NVAR * BATCH + 255) / 256, 256>>>(U);

    cudaFuncSetAttribute(sen_main, cudaFuncAttributeMaxDynamicSharedMemorySize, SMEM_TOTAL);
    sen_main<<<NCTA, 256, SMEM_TOTAL>>>(X, b1, b2, W3, b3, out);
}

// round 16
// speedup vs baseline: 1.0549x; 1.0549x over previous
#include <cuda_runtime.h>
#include <cuda_fp16.h>
#include <cstdint>

// ---------------- constants ----------------
#define NVAR   64
#define HID1   256
#define HID2   128
#define BATCH  16384
#define BT     128
#define NCTA   (BATCH / BT)        // 128 CTAs
#define KTMAX  4
#define HSH    264                 // sH row stride (halfs)
#define YCS    136                 // Yc column stride (halfs); 272B

// SMEM byte offsets (all 16B aligned)
#define OFF_YC   0                         // 67 cols x 136 halfs (pad 18432)
#define OFF_H    18432                     // 128 x 264 halfs = 67584
#define OFF_W1   86016                     // 32768 (ktc<=4)
#define OFF_W2   118784                    // 65536 (both K-halves)
#define OFF_COLS 184320                    // 2 x 80 ints (pad 768)
#define OFF_B1   185088                    // 2 x 256 f = 2048
#define OFF_B2   187136                    // 2 x 128 f = 1024
#define OFF_W3   188160                    // 2 x 128 f = 1024
#define OFF_B3   189184                    // 2 f (pad 16)
#define OFF_SP   189200                    // 4 x 128 f = 2048
#define SMEM_TOTAL 191248

// ---------------- device scratch ----------------
__device__ __half g_W1h[NVAR * 16384];     // packed compact-K frag-major (4096*ktc halfs/var)
__device__ __half g_W2h[NVAR * 32768];     // per-var full W2, frag-major
__device__ __half g_Uth[NVAR * BATCH];
__device__ int    g_plist[NVAR * NVAR];
__device__ int    g_pcnt[NVAR];
__device__ int    g_KT[NVAR];
__device__ int    g_off1[NVAR];
__device__ int    g_cols[NVAR * 80];       // per-var Yc column index per compact-k

// ---------------- helpers ----------------
static __device__ __forceinline__ void mma16(float* c, const unsigned* a,
                                             unsigned b0, unsigned b1) {
    asm volatile(
        "mma.sync.aligned.m16n8k16.row.col.f32.f16.f16.f32 "
        "{%0,%1,%2,%3},{%4,%5,%6,%7},{%8,%9},{%0,%1,%2,%3};\n"
        : "+f"(c[0]), "+f"(c[1]), "+f"(c[2]), "+f"(c[3])
        : "r"(a[0]), "r"(a[1]), "r"(a[2]), "r"(a[3]), "r"(b0), "r"(b1));
}

static __device__ __forceinline__ void ldmA(unsigned* a, uint32_t saddr) {
    asm volatile("ldmatrix.sync.aligned.m8n8.x4.shared.b16 {%0,%1,%2,%3}, [%4];"
        : "=r"(a[0]), "=r"(a[1]), "=r"(a[2]), "=r"(a[3]) : "r"(saddr));
}
static __device__ __forceinline__ void ldmT(unsigned* a, uint32_t saddr) {
    asm volatile("ldmatrix.sync.aligned.m8n8.x4.trans.shared.b16 {%0,%1,%2,%3}, [%4];"
        : "=r"(a[0]), "=r"(a[1]), "=r"(a[2]), "=r"(a[3]) : "r"(saddr));
}

static __device__ __forceinline__ void cp16(void* sdst, const void* gsrc) {
    unsigned sa = (unsigned)__cvta_generic_to_shared(sdst);
    asm volatile("cp.async.cg.shared.global [%0], [%1], 16;\n" :: "r"(sa), "l"(gsrc));
}

#define CP_COMMIT() asm volatile("cp.async.commit_group;\n" ::: "memory")
#define CP_WAIT0()  asm volatile("cp.async.wait_group 0;\n" ::: "memory")
#define BAR_SYNC(id, n) asm volatile("bar.sync %0, %1;" :: "r"(id), "r"(n) : "memory")

// ---------------- prep kernels (identical layouts to R12) ----------------
__global__ void sen_prep_meta(const int* __restrict__ G) {
    int i = threadIdx.x;
    int np = 0;
    for (int j = 0; j < i; ++j)
        if (G[j * NVAR + i] > 0) g_plist[i * NVAR + np++] = j;
    g_pcnt[i] = np;
    g_KT[i] = (np + 16) / 16;          // ceil((np+1)/16) <= 4
    for (int k = 0; k < 80; ++k) {
        int c;
        if (k < np)       c = g_plist[i * NVAR + k];
        else if (k == np) c = 64 + (i & 1);   // u column (parity)
        else              c = 66;             // zero column
        g_cols[i * 80 + k] = c;
    }
    __syncthreads();
    if (i == 0) {
        int off = 0;
        for (int v = 0; v < NVAR; ++v) { g_off1[v] = off; off += 4096 * g_KT[v]; }
    }
}

// W1 packed compact-K frag-major: chunk(i) = [hf=2][n4g=8][kt=ktc][lane=32][8 halfs]
__global__ void sen_prep_w1h(const float* __restrict__ W1) {
    int idx = blockIdx.x * blockDim.x + threadIdx.x;
    if (idx >= NVAR * 16384) return;
    int i    = idx / 16384;
    int rem  = idx % 16384;
    int hf   = rem / 8192;
    int rem2 = rem % 8192;
    int n4g  = rem2 / 1024;
    int rem3 = rem2 % 1024;
    int kt   = rem3 / 256;
    int f    = rem3 % 256;
    int lane = f >> 3, h = f & 7;
    int ktc = g_KT[i];
    if (kt >= ktc) return;
    int n8l = h >> 2, p = (h >> 1) & 1, e = h & 1;
    int k = kt * 16 + (lane & 3) * 2 + 8 * p + e;
    int n = hf * 128 + n4g * 16 + n8l * 8 + (lane >> 2);
    int np = g_pcnt[i];
    float val = 0.f;
    if (k < np)       val = W1[(i * (NVAR + 1) + g_plist[i * NVAR + k]) * HID1 + n];
    else if (k == np) val = W1[(i * (NVAR + 1) + NVAR) * HID1 + n];
    int dst = g_off1[i] + ((hf * 8 + n4g) * ktc + kt) * 256 + lane * 8 + h;
    g_W1h[dst] = __float2half_rn(val);
}

// W2 frag-major per var: [hf=2][n4g=8][kt=8][lane=32][8 halfs]
__global__ void sen_prep_w2h(const float* __restrict__ W2) {
    int idx = blockIdx.x * blockDim.x + threadIdx.x;
    if (idx >= NVAR * 32768) return;
    int i    = idx / 32768;
    int rem  = idx % 32768;
    int hf   = rem / 16384;
    int rem2 = rem % 16384;
    int n4g  = rem2 / 2048;
    int rem3 = rem2 % 2048;
    int kt   = rem3 / 256;
    int f    = rem3 % 256;
    int lane = f >> 3, h = f & 7;
    int n8l = h >> 2, p = (h >> 1) & 1, e = h & 1;
    int k = hf * 128 + kt * 16 + (lane & 3) * 2 + 8 * p + e;
    int n = n4g * 16 + n8l * 8 + (lane >> 2);
    g_W2h[idx] = __float2half_rn(W2[(i * HID1 + k) * HID2 + n]);
}

__global__ void sen_prep_ut(const float* __restrict__ U) {
    int idx = blockIdx.x * blockDim.x + threadIdx.x;
    if (idx >= NVAR * BATCH) return;
    int v = idx / BATCH;
    int b = idx - v * BATCH;
    g_Uth[idx] = __float2half_rn(U[b * NVAR + v]);
}

// ---------------- main kernel: 512 threads, fat phases ----------------
__global__ void __launch_bounds__(512, 1) sen_main(
    const float* __restrict__ X,
    const float* __restrict__ b1g,
    const float* __restrict__ b2g,
    const float* __restrict__ W3g,
    const float* __restrict__ b3g,
    float* __restrict__ out)
{
    extern __shared__ char smem[];
    __half* Yc   = (__half*)(smem + OFF_YC);
    __half* sH   = (__half*)(smem + OFF_H);
    int*   sCols = (int*)  (smem + OFF_COLS);
    float*  sB1  = (float*)(smem + OFF_B1);
    float*  sB2  = (float*)(smem + OFF_B2);
    float*  sW3  = (float*)(smem + OFF_W3);
    float*  sB3  = (float*)(smem + OFF_B3);
    float*  sP   = (float*)(smem + OFF_SP);
    const uint32_t smb = (uint32_t)__cvta_generic_to_shared(smem);
    const uint32_t ycb = smb + OFF_YC;

    const int tid  = threadIdx.x;
    const int lane = tid & 31;
    const int w    = tid >> 5;
    const int wm   = w >> 2;                // M group 0..3 (rows 32*wm..+32)
    const int wl   = w & 3;                 // N group 0..3
    const int hfw  = wl >> 1;               // L1: this warp's 128-col half
    const int n4b  = (wl & 1) * 4;          // L1: n4 base within half
    const int b0   = blockIdx.x * BT;
    const int r0   = 32 * wm + (lane >> 2);
    const int ccol = (lane & 3) * 2;
    const int laneoff = ((lane >> 4) << 3) + (lane & 7);
    const uint32_t rowb2 = (uint32_t)(32 * wm + ((lane >> 3) & 1) * 8) * 2;

    const uint32_t aHb = smb + OFF_H +
        ((((32 * wm + (lane & 15)) * HSH) + (lane >> 4) * 8) << 1);

    // init Yc cols 0..63 from X (column-major)
    for (int idx = tid; idx < NVAR * BT; idx += 512) {
        int v = idx >> 7, r = idx & 127;
        Yc[v * YCS + r] = __float2half_rn(X[(size_t)(b0 + r) * NVAR + v]);
    }
    // zero cols 64..66
    for (int idx = tid; idx < 3 * YCS; idx += 512) {
        int c = 64 + idx / YCS, p = idx % YCS;
        Yc[c * YCS + p] = __half(0.f);
    }
    __syncthreads();
    if (tid < 16) {   // u_0 into col 64 (parity 0)
        uint4 v = *(const uint4*)(g_Uth + b0 + tid * 8);
        *(uint4*)(Yc + 64 * YCS + tid * 8) = v;
    }
    if (tid < 80) sCols[tid] = __ldg(g_cols + tid);
    if (tid < 256) sB1[tid] = __ldg(b1g + tid);
    if (tid < 128) { sB2[tid] = __ldg(b2g + tid); sW3[tid] = __ldg(W3g + tid); }
    if (tid == 0) sB3[0] = __ldg(b3g);
    // issue W1(0)
    {
        const int kt0 = __ldg(g_KT);
        const char* s1 = (const char*)g_W1h;
        for (int idx = tid; idx < kt0 * 512; idx += 512)
            cp16(smem + OFF_W1 + idx * 16, s1 + idx * 16);
        CP_COMMIT();
    }

// L1 one 32-col pass (P=0,1): warp cols = wl*64 + P*32 .. +32
#define L1P(KTC, P)                                                          \
    _Pragma("unroll")                                                        \
    for (int m = 0; m < 2; ++m)                                              \
        _Pragma("unroll")                                                    \
        for (int n = 0; n < 4; ++n)                                          \
            _Pragma("unroll")                                                \
            for (int e = 0; e < 4; ++e) c1[m][n][e] = 0.f;                   \
    _Pragma("unroll")                                                        \
    for (int kt = 0; kt < (KTC); ++kt) {                                     \
        unsigned a0[4], a1[4];                                               \
        const int sc = scp[kt * 16 + laneoff];                               \
        const uint32_t aA = ycb + (uint32_t)sc * (YCS * 2) + rowb2;          \
        ldmT(a0, aA);                                                        \
        ldmT(a1, aA + 32);                                                   \
        _Pragma("unroll")                                                    \
        for (int q = 0; q < 2; ++q) {                                        \
            uint4 bb = *(const uint4*)(smem + OFF_W1 +                       \
                (((((hfw * 8 + n4b + (P) * 2 + q) * (KTC)) + kt) * 32 + lane) << 4)); \
            mma16(c1[0][q * 2],     a0, bb.x, bb.y);                         \
            mma16(c1[0][q * 2 + 1], a0, bb.z, bb.w);                         \
            mma16(c1[1][q * 2],     a1, bb.x, bb.y);                         \
            mma16(c1[1][q * 2 + 1], a1, bb.z, bb.w);                         \
        }                                                                    \
    }

#define EPIP(P) {                                                            \
    const float* B1 = sB1 + pb * 256;                                        \
    const int cb = wl * 64 + (P) * 32;                                       \
    _Pragma("unroll")                                                        \
    for (int Mt = 0; Mt < 2; ++Mt) {                                         \
        const int rA = r0 + 16 * Mt;                                         \
        _Pragma("unroll")                                                    \
        for (int n = 0; n < 4; ++n) {                                        \
            const int c = cb + n * 8 + ccol;                                 \
            const float bi0 = B1[c], bi1 = B1[c + 1];                        \
            __half2 hA = __floats2half2_rn(fmaxf(c1[Mt][n][0] + bi0, 0.f),   \
                                           fmaxf(c1[Mt][n][1] + bi1, 0.f));  \
            __half2 hB = __floats2half2_rn(fmaxf(c1[Mt][n][2] + bi0, 0.f),   \
                                           fmaxf(c1[Mt][n][3] + bi1, 0.f));  \
            *(__half2*)(sH + rA * HSH + c)       = hA;                       \
            *(__half2*)(sH + (rA + 8) * HSH + c) = hB;                       \
        } } }

    #pragma unroll 1
    for (int i = 0; i < NVAR; ++i) {
        const int pb  = i & 1;
        const int ktc = __ldg(g_KT + i);

        // S1 (CTA): W1(i) landed; Yc col i-1, u_i, sCols(i), biases(i) visible
        CP_WAIT0();
        __syncthreads();

        // ---- phase A: issue full W2(i); L1 (two passes) + epilogue ----
        {
            const char* s2 = (const char*)(g_W2h + (size_t)i * 32768);
            for (int idx = tid; idx < 4096; idx += 512)
                cp16(smem + OFF_W2 + idx * 16, s2 + idx * 16);
            CP_COMMIT();
        }
        {
            const int* scp = sCols + pb * 80;
            float c1[2][4][4];
            switch (ktc) {
                case 1: L1P(1, 0) EPIP(0) L1P(1, 1) EPIP(1) break;
                case 2: L1P(2, 0) EPIP(0) L1P(2, 1) EPIP(1) break;
                case 3: L1P(3, 0) EPIP(0) L1P(3, 1) EPIP(1) break;
                default: L1P(4, 0) EPIP(0) L1P(4, 1) EPIP(1) break;
            }
        }

        // S2 (CTA): sH complete + full W2 landed
        CP_WAIT0();
        __syncthreads();

        // ---- phase B: issue next-var W1/cols/biases/u; L2 (full K, 32 cols); L3 ----
        if (i + 1 < NVAR) {
            const int ktn = __ldg(g_KT + i + 1);
            const char* s1 = (const char*)(g_W1h + __ldg(g_off1 + i + 1));
            for (int idx = tid; idx < ktn * 512; idx += 512)
                cp16(smem + OFF_W1 + idx * 16, s1 + idx * 16);
            const int nb = (i + 1) & 1;
            if (tid < 256) sB1[nb * 256 + tid] = __ldg(b1g + (i + 1) * HID1 + tid);
            if (tid < 128) {
                sB2[nb * 128 + tid] = __ldg(b2g + (i + 1) * HID2 + tid);
                sW3[nb * 128 + tid] = __ldg(W3g + (i + 1) * HID2 + tid);
            }
            if (tid == 0) sB3[nb] = __ldg(b3g + i + 1);
            if (tid < 80) sCols[nb * 80 + tid] = __ldg(g_cols + (i + 1) * 80 + tid);
            if (tid < 16) {
                uint4 v = *(const uint4*)(g_Uth + (size_t)(i + 1) * BATCH + b0 + tid * 8);
                *(uint4*)(Yc + (64 + nb) * YCS + tid * 8) = v;
            }
        }
        CP_COMMIT();

        // L2: warp covers cols wl*32..+32, full K=256 (acc2 live only in phase B)
        float acc2[2][4][4];
        #pragma unroll
        for (int m = 0; m < 2; ++m)
            #pragma unroll
            for (int n = 0; n < 4; ++n)
                #pragma unroll
                for (int e = 0; e < 4; ++e) acc2[m][n][e] = 0.f;
        #pragma unroll
        for (int kt = 0; kt < 16; ++kt) {
            const int HF = kt >> 3, ktl = kt & 7;
            unsigned a0[4], a1[4];
            const uint32_t aH = aHb + kt * 32;
            ldmA(a0, aH);
            ldmA(a1, aH + 16 * HSH * 2);
            #pragma unroll
            for (int q = 0; q < 2; ++q) {
                uint4 bb = *(const uint4*)(smem + OFF_W2 + HF * 32768 +
                    ((((wl * 2 + q) * 8 + ktl) * 32 + lane) << 4));
                mma16(acc2[0][q * 2],     a0, bb.x, bb.y);
                mma16(acc2[0][q * 2 + 1], a0, bb.z, bb.w);
                mma16(acc2[1][q * 2],     a1, bb.x, bb.y);
                mma16(acc2[1][q * 2 + 1], a1, bb.z, bb.w);
            }
        }

        // ---- L3: y = relu(acc2 + b2) . w3 + b3 ; 4-way partials across wl ----
        {
            const float* B2  = sB2 + pb * 128;
            const float* W3s = sW3 + pb * 128;
            float yv[2][2];
            #pragma unroll
            for (int Mt = 0; Mt < 2; ++Mt) {
                float pA = 0.f, pB = 0.f;
                #pragma unroll
                for (int n = 0; n < 4; ++n) {
                    const int c = wl * 32 + n * 8 + ccol;
                    const float w30 = W3s[c], w31 = W3s[c + 1];
                    const float d0 = B2[c], d1 = B2[c + 1];
                    pA = fmaf(fmaxf(acc2[Mt][n][0] + d0, 0.f), w30, pA);
                    pA = fmaf(fmaxf(acc2[Mt][n][1] + d1, 0.f), w31, pA);
                    pB = fmaf(fmaxf(acc2[Mt][n][2] + d0, 0.f), w30, pB);
                    pB = fmaf(fmaxf(acc2[Mt][n][3] + d1, 0.f), w31, pB);
                }
                pA += __shfl_xor_sync(0xffffffffu, pA, 1);
                pA += __shfl_xor_sync(0xffffffffu, pA, 2);
                pB += __shfl_xor_sync(0xffffffffu, pB, 1);
                pB += __shfl_xor_sync(0xffffffffu, pB, 2);
                yv[Mt][0] = pA; yv[Mt][1] = pB;
            }
            if ((lane & 3) == 0) {
                sP[wl * 128 + r0]      = yv[0][0];
                sP[wl * 128 + r0 + 8]  = yv[0][1];
                sP[wl * 128 + r0 + 16] = yv[1][0];
                sP[wl * 128 + r0 + 24] = yv[1][1];
            }
            BAR_SYNC(1 + wm, 128);   // wm-group local: 4 wl warps exchange partials
            if (wl == 0 && (lane & 3) == 0) {
                const float b3v = sB3[pb];
                #pragma unroll
                for (int s = 0; s < 4; ++s) {
                    const int r = r0 + 8 * s;
                    const float y = sP[r] + sP[128 + r] + sP[256 + r] + sP[384 + r] + b3v;
                    out[(size_t)(b0 + r) * NVAR + i] = y;
                    Yc[i * YCS + r] = __float2half_rn(y);
                }
            }
        }
        // next S1 (CTA-wide) publishes Yc col i / u / cols / biases before A(i+1)
    } // i
}

#undef L1P
#undef EPIP

// ---------------- launch ----------------
extern "C" void kernel_launch(void* const* d_in, const int* in_sizes, int n_in,
                              void* d_out, int out_size) {
    (void)in_sizes; (void)n_in; (void)out_size;
    const float* X  = (const float*)d_in[0];
    const float* U  = (const float*)d_in[1];
    const int*   G  = (const int*)  d_in[2];
    const float* W1 = (const float*)d_in[3];
    const float* b1 = (const float*)d_in[4];
    const float* W2 = (const float*)d_in[5];
    const float* b2 = (const float*)d_in[6];
    const float* W3 = (const float*)d_in[7];
    const float* b3 = (const float*)d_in[8];
    float* out = (float*)d_out;

    sen_prep_meta<<<1, NVAR>>>(G);
    sen_prep_w1h<<<(NVAR * 16384 + 255) / 256, 256>>>(W1);
    sen_prep_w2h<<<(NVAR * 32768 + 255) / 256, 256>>>(W2);
    sen_prep_ut<<<(NVAR * BATCH + 255) / 256, 256>>>(U);

    cudaFuncSetAttribute(sen_main, cudaFuncAttributeMaxDynamicSharedMemorySize, SMEM_TOTAL);
    sen_main<<<NCTA, 512, SMEM_TOTAL>>>(X, b1, b2, W3, b3, out);
}

// round 17
// speedup vs baseline: 1.1180x; 1.0598x over previous
#include <cuda_runtime.h>
#include <cuda_fp16.h>
#include <cstdint>

// ---------------- constants ----------------
#define NVAR   64
#define HID1   256
#define HID2   128
#define BATCH  16384
#define BT     128
#define NCTA   (BATCH / BT)        // 128 CTAs
#define KTMAX  4
#define HSH    264                 // sH row stride (halfs)
#define YCS    136                 // Yc column stride (halfs); 272B

// SMEM byte offsets (all 16B aligned)
#define OFF_YC   0                         // 67 cols x 136 halfs (pad 18432)
#define OFF_H    18432                     // 128 x 264 halfs = 67584
#define OFF_W1   86016                     // 32768 (ktc<=4)
#define OFF_W2   118784                    // 65536 (both K-halves)
#define OFF_COLS 184320                    // 2 x 80 ints (pad 768)
#define OFF_B1   185088                    // 2 x 256 f
#define OFF_B2   187136                    // 2 x 128 f
#define OFF_W3   188160                    // 2 x 128 f
#define OFF_B3   189184                    // 2 f (pad 16)
#define OFF_SP   189200                    // 2 x 128 f
#define SMEM_TOTAL 190224

// ---------------- device scratch ----------------
__device__ __half g_W1h[NVAR * 16384];     // packed compact-K frag-major (4096*ktc halfs/var)
__device__ __half g_W2h[NVAR * 32768];     // per-var full W2, frag-major
__device__ __half g_Uth[NVAR * BATCH];
__device__ int    g_plist[NVAR * NVAR];
__device__ int    g_pcnt[NVAR];
__device__ int    g_KT[NVAR];
__device__ int    g_off1[NVAR];
__device__ int    g_cols[NVAR * 80];       // per-var Yc column index per compact-k

// ---------------- helpers ----------------
static __device__ __forceinline__ void mma16(float* c, const unsigned* a,
                                             unsigned b0, unsigned b1) {
    asm volatile(
        "mma.sync.aligned.m16n8k16.row.col.f32.f16.f16.f32 "
        "{%0,%1,%2,%3},{%4,%5,%6,%7},{%8,%9},{%0,%1,%2,%3};\n"
        : "+f"(c[0]), "+f"(c[1]), "+f"(c[2]), "+f"(c[3])
        : "r"(a[0]), "r"(a[1]), "r"(a[2]), "r"(a[3]), "r"(b0), "r"(b1));
}

static __device__ __forceinline__ void ldmA(unsigned* a, uint32_t saddr) {
    asm volatile("ldmatrix.sync.aligned.m8n8.x4.shared.b16 {%0,%1,%2,%3}, [%4];"
        : "=r"(a[0]), "=r"(a[1]), "=r"(a[2]), "=r"(a[3]) : "r"(saddr));
}
static __device__ __forceinline__ void ldmT(unsigned* a, uint32_t saddr) {
    asm volatile("ldmatrix.sync.aligned.m8n8.x4.trans.shared.b16 {%0,%1,%2,%3}, [%4];"
        : "=r"(a[0]), "=r"(a[1]), "=r"(a[2]), "=r"(a[3]) : "r"(saddr));
}

static __device__ __forceinline__ void cp16(void* sdst, const void* gsrc) {
    unsigned sa = (unsigned)__cvta_generic_to_shared(sdst);
    asm volatile("cp.async.cg.shared.global [%0], [%1], 16;\n" :: "r"(sa), "l"(gsrc));
}

#define CP_COMMIT() asm volatile("cp.async.commit_group;\n" ::: "memory")
#define CP_WAIT0()  asm volatile("cp.async.wait_group 0;\n" ::: "memory")
#define BAR_SYNC(id, n) asm volatile("bar.sync %0, %1;" :: "r"(id), "r"(n) : "memory")

// ---------------- prep kernels (identical to R12) ----------------
__global__ void sen_prep_meta(const int* __restrict__ G) {
    int i = threadIdx.x;
    int np = 0;
    for (int j = 0; j < i; ++j)
        if (G[j * NVAR + i] > 0) g_plist[i * NVAR + np++] = j;
    g_pcnt[i] = np;
    g_KT[i] = (np + 16) / 16;          // ceil((np+1)/16) <= 4
    for (int k = 0; k < 80; ++k) {
        int c;
        if (k < np)       c = g_plist[i * NVAR + k];
        else if (k == np) c = 64 + (i & 1);   // u column (parity)
        else              c = 66;             // zero column
        g_cols[i * 80 + k] = c;
    }
    __syncthreads();
    if (i == 0) {
        int off = 0;
        for (int v = 0; v < NVAR; ++v) { g_off1[v] = off; off += 4096 * g_KT[v]; }
    }
}

// W1 packed compact-K frag-major: chunk(i) = [hf=2][n4g=8][kt=ktc][lane=32][8 halfs]
__global__ void sen_prep_w1h(const float* __restrict__ W1) {
    int idx = blockIdx.x * blockDim.x + threadIdx.x;
    if (idx >= NVAR * 16384) return;
    int i    = idx / 16384;
    int rem  = idx % 16384;
    int hf   = rem / 8192;
    int rem2 = rem % 8192;
    int n4g  = rem2 / 1024;
    int rem3 = rem2 % 1024;
    int kt   = rem3 / 256;
    int f    = rem3 % 256;
    int lane = f >> 3, h = f & 7;
    int ktc = g_KT[i];
    if (kt >= ktc) return;
    int n8l = h >> 2, p = (h >> 1) & 1, e = h & 1;
    int k = kt * 16 + (lane & 3) * 2 + 8 * p + e;
    int n = hf * 128 + n4g * 16 + n8l * 8 + (lane >> 2);
    int np = g_pcnt[i];
    float val = 0.f;
    if (k < np)       val = W1[(i * (NVAR + 1) + g_plist[i * NVAR + k]) * HID1 + n];
    else if (k == np) val = W1[(i * (NVAR + 1) + NVAR) * HID1 + n];
    int dst = g_off1[i] + ((hf * 8 + n4g) * ktc + kt) * 256 + lane * 8 + h;
    g_W1h[dst] = __float2half_rn(val);
}

// W2 frag-major per var: [hf=2][n4g=8][kt=8][lane=32][8 halfs]
__global__ void sen_prep_w2h(const float* __restrict__ W2) {
    int idx = blockIdx.x * blockDim.x + threadIdx.x;
    if (idx >= NVAR * 32768) return;
    int i    = idx / 32768;
    int rem  = idx % 32768;
    int hf   = rem / 16384;
    int rem2 = rem % 16384;
    int n4g  = rem2 / 2048;
    int rem3 = rem2 % 2048;
    int kt   = rem3 / 256;
    int f    = rem3 % 256;
    int lane = f >> 3, h = f & 7;
    int n8l = h >> 2, p = (h >> 1) & 1, e = h & 1;
    int k = hf * 128 + kt * 16 + (lane & 3) * 2 + 8 * p + e;
    int n = n4g * 16 + n8l * 8 + (lane >> 2);
    g_W2h[idx] = __float2half_rn(W2[(i * HID1 + k) * HID2 + n]);
}

__global__ void sen_prep_ut(const float* __restrict__ U) {
    int idx = blockIdx.x * blockDim.x + threadIdx.x;
    if (idx >= NVAR * BATCH) return;
    int v = idx / BATCH;
    int b = idx - v * BATCH;
    g_Uth[idx] = __float2half_rn(U[b * NVAR + v]);
}

// ---------------- main kernel ----------------
__global__ void __launch_bounds__(256, 1) sen_main(
    const float* __restrict__ X,
    const float* __restrict__ b1g,
    const float* __restrict__ b2g,
    const float* __restrict__ W3g,
    const float* __restrict__ b3g,
    float* __restrict__ out)
{
    extern __shared__ char smem[];
    __half* Yc   = (__half*)(smem + OFF_YC);
    __half* sH   = (__half*)(smem + OFF_H);
    int*   sCols = (int*)  (smem + OFF_COLS);
    float*  sB1  = (float*)(smem + OFF_B1);
    float*  sB2  = (float*)(smem + OFF_B2);
    float*  sW3  = (float*)(smem + OFF_W3);
    float*  sB3  = (float*)(smem + OFF_B3);
    float*  sP   = (float*)(smem + OFF_SP);
    const uint32_t smb = (uint32_t)__cvta_generic_to_shared(smem);
    const uint32_t ycb = smb + OFF_YC;

    const int tid  = threadIdx.x;
    const int lane = tid & 31;
    const int w    = tid >> 5;
    const int wm   = w >> 1;                // M group 0..3 (pair id)
    const int wn   = w & 1;                 // N group 0..1
    const int b0   = blockIdx.x * BT;
    const int r0   = 32 * wm + (lane >> 2);
    const int ccol = (lane & 3) * 2;
    const int laneoff = ((lane >> 4) << 3) + (lane & 7);
    const uint32_t rowb2 = (uint32_t)(32 * wm + ((lane >> 3) & 1) * 8) * 2;

    const uint32_t aHb = smb + OFF_H +
        ((((32 * wm + (lane & 15)) * HSH) + (lane >> 4) * 8) << 1);

    // init Yc cols 0..63 from X (column-major)
    for (int idx = tid; idx < NVAR * BT; idx += 256) {
        int v = idx >> 7, r = idx & 127;
        Yc[v * YCS + r] = __float2half_rn(X[(size_t)(b0 + r) * NVAR + v]);
    }
    // zero cols 64..66
    for (int idx = tid; idx < 3 * YCS; idx += 256) {
        int c = 64 + idx / YCS, p = idx % YCS;
        Yc[c * YCS + p] = __half(0.f);
    }
    __syncthreads();
    if (tid < 16) {   // u_0 into col 64 (parity 0)
        uint4 v = *(const uint4*)(g_Uth + b0 + tid * 8);
        *(uint4*)(Yc + 64 * YCS + tid * 8) = v;
    }
    if (tid < 80) sCols[tid] = __ldg(g_cols + tid);
    sB1[tid] = __ldg(b1g + tid);
    if (tid < 128) { sB2[tid] = __ldg(b2g + tid); sW3[tid] = __ldg(W3g + tid); }
    if (tid == 0) sB3[0] = __ldg(b3g);
    // issue W1(0)
    {
        const int kt0 = __ldg(g_KT);
        const char* s1 = (const char*)g_W1h;
        for (int idx = tid; idx < kt0 * 512; idx += 256)
            cp16(smem + OFF_W1 + idx * 16, s1 + idx * 16);
        CP_COMMIT();
    }

    float acc2[2][8][4];
    #pragma unroll
    for (int m = 0; m < 2; ++m)
        #pragma unroll
        for (int n = 0; n < 8; ++n)
            #pragma unroll
            for (int e = 0; e < 4; ++e) acc2[m][n][e] = 0.f;

// L1 one N-half via indexed ldmatrix.trans from Yc
#define L1H(KTC, HF)                                                         \
    _Pragma("unroll")                                                        \
    for (int m = 0; m < 2; ++m)                                              \
        _Pragma("unroll")                                                    \
        for (int n = 0; n < 8; ++n)                                          \
            _Pragma("unroll")                                                \
            for (int e = 0; e < 4; ++e) c1[m][n][e] = 0.f;                   \
    _Pragma("unroll")                                                        \
    for (int kt = 0; kt < (KTC); ++kt) {                                     \
        unsigned a0[4], a1[4];                                               \
        const int sc = scp[kt * 16 + laneoff];                               \
        const uint32_t aA = ycb + (uint32_t)sc * (YCS * 2) + rowb2;          \
        ldmT(a0, aA);                                                        \
        ldmT(a1, aA + 32);                                                   \
        _Pragma("unroll")                                                    \
        for (int n4 = 0; n4 < 4; ++n4) {                                     \
            uint4 bb = *(const uint4*)(smem + OFF_W1 +                       \
                ((((((HF) * 8 + wn * 4 + n4) * (KTC)) + kt) * 32 + lane) << 4)); \
            mma16(c1[0][n4 * 2],     a0, bb.x, bb.y);                        \
            mma16(c1[0][n4 * 2 + 1], a0, bb.z, bb.w);                        \
            mma16(c1[1][n4 * 2],     a1, bb.x, bb.y);                        \
            mma16(c1[1][n4 * 2 + 1], a1, bb.z, bb.w);                        \
        }                                                                    \
    }

#define EPI(HF) {                                                            \
    const float* B1 = sB1 + pb * 256;                                        \
    _Pragma("unroll")                                                        \
    for (int Mt = 0; Mt < 2; ++Mt) {                                         \
        const int rA = r0 + 16 * Mt;                                         \
        _Pragma("unroll")                                                    \
        for (int n = 0; n < 8; ++n) {                                        \
            const int c = (HF) * 128 + wn * 64 + n * 8 + ccol;               \
            const float bi0 = B1[c], bi1 = B1[c + 1];                        \
            __half2 hA = __floats2half2_rn(fmaxf(c1[Mt][n][0] + bi0, 0.f),   \
                                           fmaxf(c1[Mt][n][1] + bi1, 0.f));  \
            __half2 hB = __floats2half2_rn(fmaxf(c1[Mt][n][2] + bi0, 0.f),   \
                                           fmaxf(c1[Mt][n][3] + bi1, 0.f));  \
            *(__half2*)(sH + rA * HSH + c)       = hA;                       \
            *(__half2*)(sH + (rA + 8) * HSH + c) = hB;                       \
        } } }

#define L2H(HF)                                                              \
    _Pragma("unroll")                                                        \
    for (int kt = 0; kt < 8; ++kt) {                                         \
        unsigned a0[4], a1[4];                                               \
        const uint32_t aH = aHb + ((HF) * 8 + kt) * 32;                      \
        ldmA(a0, aH);                                                        \
        ldmA(a1, aH + 16 * HSH * 2);                                         \
        _Pragma("unroll")                                                    \
        for (int n4 = 0; n4 < 4; ++n4) {                                     \
            uint4 bb = *(const uint4*)(smem + OFF_W2 + (HF) * 32768 +        \
                ((((wn * 4 + n4) * 8 + kt) * 32 + lane) << 4));              \
            mma16(acc2[0][n4 * 2],     a0, bb.x, bb.y);                      \
            mma16(acc2[0][n4 * 2 + 1], a0, bb.z, bb.w);                      \
            mma16(acc2[1][n4 * 2],     a1, bb.x, bb.y);                      \
            mma16(acc2[1][n4 * 2 + 1], a1, bb.z, bb.w);                      \
        }                                                                    \
    }

    #pragma unroll 1
    for (int i = 0; i < NVAR; ++i) {
        const int pb  = i & 1;
        const int ktc = __ldg(g_KT + i);

        // S1 (CTA): W1(i) landed; Yc col i-1, u_i, sCols(i), biases(i) visible
        CP_WAIT0();
        __syncthreads();

        // ---- phase A: issue full W2(i); L1 (indexed) + epilogue ----
        {
            const char* s2 = (const char*)(g_W2h + (size_t)i * 32768);
            for (int idx = tid; idx < 4096; idx += 256)
                cp16(smem + OFF_W2 + idx * 16, s2 + idx * 16);
            CP_COMMIT();
        }
        {
            const int* scp = sCols + pb * 80;
            float c1[2][8][4];
            switch (ktc) {
                case 1: L1H(1, 0) EPI(0) L1H(1, 1) EPI(1) break;
                case 2: L1H(2, 0) EPI(0) L1H(2, 1) EPI(1) break;
                case 3: L1H(3, 0) EPI(0) L1H(3, 1) EPI(1) break;
                default: L1H(4, 0) EPI(0) L1H(4, 1) EPI(1) break;
            }
        }

        // S2 (CTA): sH complete + full W2 landed (W2 visibility is cross-warp)
        CP_WAIT0();
        __syncthreads();

        // ---- phase B: issue next-var W1/cols/biases/u; L2 both halves; L3 ----
        if (i + 1 < NVAR) {
            const int ktn = __ldg(g_KT + i + 1);
            const char* s1 = (const char*)(g_W1h + __ldg(g_off1 + i + 1));
            for (int idx = tid; idx < ktn * 512; idx += 256)
                cp16(smem + OFF_W1 + idx * 16, s1 + idx * 16);
            const int nb = (i + 1) & 1;
            sB1[nb * 256 + tid] = __ldg(b1g + (i + 1) * HID1 + tid);
            if (tid < 128) {
                sB2[nb * 128 + tid] = __ldg(b2g + (i + 1) * HID2 + tid);
                sW3[nb * 128 + tid] = __ldg(W3g + (i + 1) * HID2 + tid);
            }
            if (tid == 0) sB3[nb] = __ldg(b3g + i + 1);
            if (tid < 80) sCols[nb * 80 + tid] = __ldg(g_cols + (i + 1) * 80 + tid);
            if (tid < 16) {
                uint4 v = *(const uint4*)(g_Uth + (size_t)(i + 1) * BATCH + b0 + tid * 8);
                *(uint4*)(Yc + (64 + nb) * YCS + tid * 8) = v;
            }
        }
        CP_COMMIT();

        L2H(0)
        L2H(1)

        // ---- L3: y = relu(acc2 + b2) . w3 + b3 (pair-local reduction) ----
        {
            const float* B2  = sB2 + pb * 128;
            const float* W3s = sW3 + pb * 128;
            float yv[2][2];
            #pragma unroll
            for (int Mt = 0; Mt < 2; ++Mt) {
                float pA = 0.f, pB = 0.f;
                #pragma unroll
                for (int n = 0; n < 8; ++n) {
                    const int c = wn * 64 + n * 8 + ccol;
                    const float w30 = W3s[c], w31 = W3s[c + 1];
                    const float d0 = B2[c], d1 = B2[c + 1];
                    pA = fmaf(fmaxf(acc2[Mt][n][0] + d0, 0.f), w30, pA);
                    pA = fmaf(fmaxf(acc2[Mt][n][1] + d1, 0.f), w31, pA);
                    pB = fmaf(fmaxf(acc2[Mt][n][2] + d0, 0.f), w30, pB);
                    pB = fmaf(fmaxf(acc2[Mt][n][3] + d1, 0.f), w31, pB);
                    acc2[Mt][n][0] = 0.f; acc2[Mt][n][1] = 0.f;
                    acc2[Mt][n][2] = 0.f; acc2[Mt][n][3] = 0.f;
                }
                pA += __shfl_xor_sync(0xffffffffu, pA, 1);
                pA += __shfl_xor_sync(0xffffffffu, pA, 2);
                pB += __shfl_xor_sync(0xffffffffu, pB, 1);
                pB += __shfl_xor_sync(0xffffffffu, pB, 2);
                yv[Mt][0] = pA; yv[Mt][1] = pB;
            }
            if ((lane & 3) == 0) {
                sP[wn * 128 + r0]      = yv[0][0];
                sP[wn * 128 + r0 + 8]  = yv[0][1];
                sP[wn * 128 + r0 + 16] = yv[1][0];
                sP[wn * 128 + r0 + 24] = yv[1][1];
            }
            BAR_SYNC(1 + wm, 64);   // pair-local: sP exchange within (wm, wn0/wn1)
            if (wn == 0) {          // all 32 lanes: one row each (r = 32*wm + lane)
                const int r = 32 * wm + lane;
                const float y = sP[r] + sP[128 + r] + sB3[pb];
                out[(size_t)(b0 + r) * NVAR + i] = y;
                Yc[i * YCS + r] = __float2half_rn(y);
            }
        }
        // next S1 (CTA-wide) publishes Yc col i / u / cols / biases cross-pair
    } // i
}

#undef L1H
#undef EPI
#undef L2H

// ---------------- launch ----------------
extern "C" void kernel_launch(void* const* d_in, const int* in_sizes, int n_in,
                              void* d_out, int out_size) {
    (void)in_sizes; (void)n_in; (void)out_size;
    const float* X  = (const float*)d_in[0];
    const float* U  = (const float*)d_in[1];
    const int*   G  = (const int*)  d_in[2];
    const float* W1 = (const float*)d_in[3];
    const float* b1 = (const float*)d_in[4];
    const float* W2 = (const float*)d_in[5];
    const float* b2 = (const float*)d_in[6];
    const float* W3 = (const float*)d_in[7];
    const float* b3 = (const float*)d_in[8];
    float* out = (float*)d_out;

    sen_prep_meta<<<1, NVAR>>>(G);
    sen_prep_w1h<<<(NVAR * 16384 + 255) / 256, 256>>>(W1);
    sen_prep_w2h<<<(NVAR * 32768 + 255) / 256, 256>>>(W2);
    sen_prep_ut<<<(NVAR * BATCH + 255) / 256, 256>>>(U);

    cudaFuncSetAttribute(sen_main, cudaFuncAttributeMaxDynamicSharedMemorySize, SMEM_TOTAL);
    sen_main<<<NCTA, 256, SMEM_TOTAL>>>(X, b1, b2, W3, b3, out);
}